// round 4
// baseline (speedup 1.0000x reference)
#include <cuda_runtime.h>

#define MAXDISP 48
#define NG      40
#define CPG     8
#define CCH     12
#define CIN1    64
#define CO      32
#define BB      4
#define HH_     64
#define WW_     128
#define DD_     48
#define HW      (HH_*WW_)     /* 8192 */
#define DHW     ((size_t)DD_*HW)  /* 393216 */

// Scratch (device globals — no allocation APIs used)
__device__ float g_vol[(size_t)BB*CIN1*DD_*HH_*WW_];  // 100,663,296 floats
__device__ float g_x1 [(size_t)BB*CO  *DD_*HH_*WW_];  //  50,331,648 floats

// ---------------------------------------------------------------------------
// Kernel 1: build cost volume
//   vol[b, g, d, h, w]      = (w>=d) ? mean_c lg[b,g*8+c,h,w]*rg[b,g*8+c,h,w-d] : 0
//   vol[b, 40+c, d, h, w]   = (w>=d) ? lc[b,c,h,w]   : 0
//   vol[b, 52+c, d, h, w]   = (w>=d) ? rc[b,c,h,w-d] : 0
// One block per (b,h) row. lg/rg rows staged in smem in chunks of 4 groups.
// ---------------------------------------------------------------------------
__global__ __launch_bounds__(256)
void build_volume_kernel(const float* __restrict__ lg,
                         const float* __restrict__ rg,
                         const float* __restrict__ lc,
                         const float* __restrict__ rc)
{
    __shared__ float lgs[32][WW_];
    __shared__ float rgs[32][WW_];

    const int b   = blockIdx.x / HH_;
    const int h   = blockIdx.x % HH_;
    const int tid = threadIdx.x;
    const int w   = tid & 127;
    const int t2  = tid >> 7;   // 0..1

    // ---- correlation groups, 4 groups (32 channels) per chunk ----
    for (int chunk = 0; chunk < NG / 4; ++chunk) {
        for (int i = tid; i < 32 * WW_; i += 256) {
            int ch = i >> 7;
            int ww = i & 127;
            int cg = chunk * 32 + ch;
            lgs[ch][ww] = lg[((size_t)(b * 320 + cg) * HH_ + h) * WW_ + ww];
            rgs[ch][ww] = rg[((size_t)(b * 320 + cg) * HH_ + h) * WW_ + ww];
        }
        __syncthreads();

        for (int gi = 0; gi < 2; ++gi) {
            int g = t2 + gi * 2;             // local group 0..3
            float lreg[CPG];
            #pragma unroll
            for (int c = 0; c < CPG; ++c) lreg[c] = lgs[g * CPG + c][w];

            int gout = chunk * 4 + g;        // global group 0..39
            float* outp = g_vol + (size_t)(b * CIN1 + gout) * DHW + (size_t)h * WW_ + w;
            // unroll by 4 to batch the strided STGs (higher store MLP)
            #pragma unroll 4
            for (int d = 0; d < DD_; ++d) {
                float v = 0.f;
                if (w >= d) {
                    float s = 0.f;
                    #pragma unroll
                    for (int c = 0; c < CPG; ++c)
                        s += lreg[c] * rgs[g * CPG + c][w - d];
                    v = s * (1.0f / CPG);
                }
                outp[(size_t)d * HW] = v;
            }
        }
        __syncthreads();
    }

    // ---- concat channels (reuse lgs) ----
    for (int i = tid; i < 24 * WW_; i += 256) {
        int ch = i >> 7;
        int ww = i & 127;
        lgs[ch][ww] = (ch < 12)
            ? lc[((size_t)(b * CCH + ch)      * HH_ + h) * WW_ + ww]
            : rc[((size_t)(b * CCH + (ch-12)) * HH_ + h) * WW_ + ww];
    }
    __syncthreads();

    for (int idx = t2; idx < 24 * DD_; idx += 2) {
        int ch = idx / DD_;
        int d  = idx % DD_;
        float v = 0.f;
        if (w >= d) v = (ch < 12) ? lgs[ch][w] : lgs[ch][w - d];
        g_vol[(size_t)(b * CIN1 + 40 + ch) * DHW + (size_t)d * HW + (size_t)h * WW_ + w] = v;
    }
}

// ---------------------------------------------------------------------------
// Kernel 2/3: 3x3x3 conv + BN + ReLU, direct tiled fp32
//   Block tile: (TD=4, TH=4, TW=32) spatial x all 32 output channels.
//   Input halo (Cin chunked by 4) and weights staged in smem.
//   Thread: 2 (d,h)-positions x 8 co x 4 w accumulators = 64 regs.
// ---------------------------------------------------------------------------
template<int CIN>
__global__ __launch_bounds__(256)
void conv3d_bn_relu(const float* __restrict__ in,
                    const float* __restrict__ wgt,     // [CO][CIN][3][3][3]
                    const float* __restrict__ gamma,
                    const float* __restrict__ beta,
                    const float* __restrict__ mean,
                    const float* __restrict__ var,
                    float* __restrict__ out)
{
    const int CC = 4;
    __shared__ float s_in[CC * 6 * 6 * 34];   // 4896 floats
    __shared__ float s_w [CC * 27 * 32];      // 3456 floats  [c][k][co]

    const int wt = blockIdx.x;            // 0..3
    const int ht = blockIdx.y;            // 0..15
    const int b  = blockIdx.z / 12;
    const int dt = blockIdx.z % 12;
    const int d0 = dt * 4, h0 = ht * 4, w0 = wt * 32;

    const int tid = threadIdx.x;
    const int cob = (tid >> 6) * 8;       // 0,8,16,24
    const int sp  = tid & 63;
    const int wb  = (sp & 7) * 4;         // 0..28
    const int dh2 = sp >> 3;              // 0..7

    float acc[2][8][4];
    #pragma unroll
    for (int i = 0; i < 2; ++i)
        #pragma unroll
        for (int o = 0; o < 8; ++o)
            #pragma unroll
            for (int j = 0; j < 4; ++j) acc[i][o][j] = 0.f;

    for (int ci0 = 0; ci0 < CIN; ci0 += CC) {
        // load input tile (with halo, zero-padded)
        for (int i = tid; i < CC * 1224; i += 256) {
            int c  = i / 1224;
            int r  = i % 1224;
            int dd = r / 204;
            int r2 = r % 204;
            int hh = r2 / 34;
            int ww = r2 % 34;
            int id = d0 + dd - 1;
            int ih = h0 + hh - 1;
            int iw = w0 + ww - 1;
            float v = 0.f;
            if (id >= 0 && id < DD_ && ih >= 0 && ih < HH_ && iw >= 0 && iw < WW_)
                v = in[(((size_t)(b * CIN + ci0 + c) * DD_ + id) * HH_ + ih) * WW_ + iw];
            s_in[i] = v;
        }
        // load weights: s_w[(c*27+k)*32+co] = wgt[(co*CIN + ci0+c)*27 + k]
        for (int i = tid; i < CC * 27 * 32; i += 256) {
            int co = i & 31;
            int ck = i >> 5;
            int c  = ck / 27;
            int k  = ck % 27;
            s_w[i] = wgt[((size_t)co * CIN + ci0 + c) * 27 + k];
        }
        __syncthreads();

        #pragma unroll 1
        for (int c = 0; c < CC; ++c) {
            #pragma unroll
            for (int kd = 0; kd < 3; ++kd)
            #pragma unroll
            for (int kh = 0; kh < 3; ++kh)
            #pragma unroll
            for (int kw = 0; kw < 3; ++kw) {
                const int k = (kd * 3 + kh) * 3 + kw;
                float wreg[8];
                #pragma unroll
                for (int o = 0; o < 8; ++o)
                    wreg[o] = s_w[(c * 27 + k) * 32 + cob + o];
                #pragma unroll
                for (int i = 0; i < 2; ++i) {
                    const int dhi = dh2 * 2 + i;
                    const int dl = dhi >> 2, hl = dhi & 3;
                    float iv[4];
                    #pragma unroll
                    for (int j = 0; j < 4; ++j)
                        iv[j] = s_in[c * 1224 + (dl + kd) * 204 + (hl + kh) * 34 + wb + kw + j];
                    #pragma unroll
                    for (int o = 0; o < 8; ++o)
                        #pragma unroll
                        for (int j = 0; j < 4; ++j)
                            acc[i][o][j] = fmaf(iv[j], wreg[o], acc[i][o][j]);
                }
            }
        }
        __syncthreads();
    }

    // epilogue: BN + ReLU, vectorized stores
    #pragma unroll
    for (int o = 0; o < 8; ++o) {
        const int co = cob + o;
        const float inv = gamma[co] * rsqrtf(var[co] + 1e-5f);
        const float sh  = beta[co] - mean[co] * inv;
        #pragma unroll
        for (int i = 0; i < 2; ++i) {
            const int dhi = dh2 * 2 + i;
            const int dl = dhi >> 2, hl = dhi & 3;
            float4 v;
            v.x = fmaxf(acc[i][o][0] * inv + sh, 0.f);
            v.y = fmaxf(acc[i][o][1] * inv + sh, 0.f);
            v.z = fmaxf(acc[i][o][2] * inv + sh, 0.f);
            v.w = fmaxf(acc[i][o][3] * inv + sh, 0.f);
            size_t oidx = (((size_t)(b * CO + co) * DD_ + d0 + dl) * HH_ + h0 + hl) * WW_ + w0 + wb;
            *reinterpret_cast<float4*>(out + oidx) = v;
        }
    }
}

// ---------------------------------------------------------------------------

extern "C" void kernel_launch(void* const* d_in, const int* in_sizes, int n_in,
                              void* d_out, int out_size)
{
    const float* lg = (const float*)d_in[0];
    const float* rg = (const float*)d_in[1];
    const float* lc = (const float*)d_in[2];
    const float* rc = (const float*)d_in[3];
    const float* w1 = (const float*)d_in[4];
    const float* g1 = (const float*)d_in[5];
    const float* b1 = (const float*)d_in[6];
    const float* m1 = (const float*)d_in[7];
    const float* v1 = (const float*)d_in[8];
    const float* w2 = (const float*)d_in[9];
    const float* g2 = (const float*)d_in[10];
    const float* b2 = (const float*)d_in[11];
    const float* m2 = (const float*)d_in[12];
    const float* v2 = (const float*)d_in[13];
    float* out = (float*)d_out;

    float* vol = nullptr;
    float* x1  = nullptr;
    cudaGetSymbolAddress((void**)&vol, g_vol);
    cudaGetSymbolAddress((void**)&x1,  g_x1);

    // 1) cost volume
    build_volume_kernel<<<BB * HH_, 256>>>(lg, rg, lc, rc);

    // 2) conv1 + BN + ReLU  (64 -> 32)
    dim3 grid(4, 16, BB * 12);
    conv3d_bn_relu<CIN1><<<grid, 256>>>(vol, w1, g1, b1, m1, v1, x1);

    // 3) conv2 + BN + ReLU  (32 -> 32)
    conv3d_bn_relu<CO><<<grid, 256>>>(x1, w2, g2, b2, m2, v2, out);
}

// round 5
// speedup vs baseline: 1.2113x; 1.2113x over previous
#include <cuda_runtime.h>
#include <cstdint>

#define MAXDISP 48
#define NG      40
#define CPG     8
#define CCH     12
#define CIN1    64
#define CO      32
#define BB      4
#define HH_     64
#define WW_     128
#define DD_     48
#define HW      (HH_*WW_)         /* 8192 */
#define DHW     ((size_t)DD_*HW)  /* 393216 */

// Scratch (device globals — no allocation APIs used)
__device__ float g_vol[(size_t)BB*CIN1*DD_*HH_*WW_];
__device__ float g_x1 [(size_t)BB*CO  *DD_*HH_*WW_];

// Packed fp32x2 FMA (Blackwell): d = a*b + d per 32-bit half, exact fp32.
#define FFMA2(acc, a, b) \
    asm volatile("fma.rn.f32x2 %0, %1, %2, %0;" : "+l"(acc) : "l"(a), "l"(b))
#define PACK2(dst, lo, hi) \
    asm volatile("mov.b64 %0, {%1, %2};" : "=l"(dst) : "f"(lo), "f"(hi))
#define UNPACK2(lo, hi, src) \
    asm volatile("mov.b64 {%0, %1}, %2;" : "=f"(lo), "=f"(hi) : "l"(src))

// ---------------------------------------------------------------------------
// Kernel 1: build cost volume.  blockIdx.x = b*64+h, blockIdx.y = chunk (0..10)
//   chunks 0..9: 4 correlation groups each; chunk 10: concat channels.
// ---------------------------------------------------------------------------
__global__ __launch_bounds__(256)
void build_volume_kernel(const float* __restrict__ lg,
                         const float* __restrict__ rg,
                         const float* __restrict__ lc,
                         const float* __restrict__ rc)
{
    __shared__ float lgs[32][WW_];
    __shared__ float rgs[32][WW_];

    const int b     = blockIdx.x / HH_;
    const int h     = blockIdx.x % HH_;
    const int chunk = blockIdx.y;
    const int tid   = threadIdx.x;
    const int w     = tid & 127;
    const int t2    = tid >> 7;   // 0..1

    if (chunk < 10) {
        // ---- 4 correlation groups (32 channels) ----
        for (int i = tid; i < 32 * WW_; i += 256) {
            int ch = i >> 7;
            int ww = i & 127;
            int cg = chunk * 32 + ch;
            lgs[ch][ww] = lg[((size_t)(b * 320 + cg) * HH_ + h) * WW_ + ww];
            rgs[ch][ww] = rg[((size_t)(b * 320 + cg) * HH_ + h) * WW_ + ww];
        }
        __syncthreads();

        for (int gi = 0; gi < 2; ++gi) {
            int g = t2 + gi * 2;             // local group 0..3
            float lreg[CPG];
            #pragma unroll
            for (int c = 0; c < CPG; ++c) lreg[c] = lgs[g * CPG + c][w];

            int gout = chunk * 4 + g;
            float* outp = g_vol + (size_t)(b * CIN1 + gout) * DHW + (size_t)h * WW_ + w;
            #pragma unroll 4
            for (int d = 0; d < DD_; ++d) {
                float v = 0.f;
                if (w >= d) {
                    float s = 0.f;
                    #pragma unroll
                    for (int c = 0; c < CPG; ++c)
                        s += lreg[c] * rgs[g * CPG + c][w - d];
                    v = s * (1.0f / CPG);
                }
                outp[(size_t)d * HW] = v;
            }
        }
    } else {
        // ---- concat channels ----
        for (int i = tid; i < 24 * WW_; i += 256) {
            int ch = i >> 7;
            int ww = i & 127;
            lgs[ch][ww] = (ch < 12)
                ? lc[((size_t)(b * CCH + ch)      * HH_ + h) * WW_ + ww]
                : rc[((size_t)(b * CCH + (ch-12)) * HH_ + h) * WW_ + ww];
        }
        __syncthreads();

        for (int idx = t2; idx < 24 * DD_; idx += 2) {
            int ch = idx / DD_;
            int d  = idx % DD_;
            float v = 0.f;
            if (w >= d) v = (ch < 12) ? lgs[ch][w] : lgs[ch][w - d];
            g_vol[(size_t)(b * CIN1 + 40 + ch) * DHW + (size_t)d * HW + (size_t)h * WW_ + w] = v;
        }
    }
}

// ---------------------------------------------------------------------------
// Kernel 2/3: 3x3x3 conv + BN + ReLU via packed fma.rn.f32x2.
//   Block tile: (TD=4, TH=4, TW=32) spatial x all 32 output channels.
//   Packed dimension = output-channel pairs: weight pairs come straight from
//   aligned LDS.64; input broadcasts packed once per 6-wide row window.
//   Thread: 2 (d,h)-pos x 4 co-pairs x 4 w = 32 x f32x2 accumulators.
// ---------------------------------------------------------------------------
#define SW_ROW 36            /* padded row stride (16B aligned) */
#define SIN_H  216           /* 6*36 */
#define SIN_C  1296          /* 6*6*36 */

template<int CIN>
__global__ __launch_bounds__(256, 2)
void conv3d_bn_relu(const float* __restrict__ in,
                    const float* __restrict__ wgt,     // [CO][CIN][3][3][3]
                    const float* __restrict__ gamma,
                    const float* __restrict__ beta,
                    const float* __restrict__ mean,
                    const float* __restrict__ var,
                    float* __restrict__ out)
{
    const int CC = 4;
    __shared__ __align__(16) float s_in[CC * SIN_C];   // 5184 f = 20.7 KB
    __shared__ __align__(16) float s_w [CC * 27 * 32]; // 3456 f = 13.8 KB

    const int wt = blockIdx.x;            // 0..3
    const int ht = blockIdx.y;            // 0..15
    const int b  = blockIdx.z / 12;
    const int dt = blockIdx.z % 12;
    const int d0 = dt * 4, h0 = ht * 4, w0 = wt * 32;

    const int tid = threadIdx.x;
    const int cob = (tid >> 6) * 8;       // 0,8,16,24
    const int sp  = tid & 63;
    const int wb  = (sp & 7) * 4;         // 0..28
    const int dh2 = sp >> 3;              // 0..7

    uint64_t acc2[2][4][4];               // [i][co-pair][w]
    #pragma unroll
    for (int i = 0; i < 2; ++i)
        #pragma unroll
        for (int op = 0; op < 4; ++op)
            #pragma unroll
            for (int j = 0; j < 4; ++j) acc2[i][op][j] = 0ull;

    for (int ci0 = 0; ci0 < CIN; ci0 += CC) {
        // load input tile (with halo, zero-padded, padded row stride 36)
        for (int i = tid; i < CC * SIN_C; i += 256) {
            int c  = i / SIN_C;
            int r  = i % SIN_C;
            int dd = r / SIN_H;
            int r2 = r % SIN_H;
            int hh = r2 / SW_ROW;
            int ww = r2 % SW_ROW;
            int id = d0 + dd - 1;
            int ih = h0 + hh - 1;
            int iw = w0 + ww - 1;
            float v = 0.f;
            if (id >= 0 && id < DD_ && ih >= 0 && ih < HH_ && iw >= 0 && iw < WW_ && ww < 34)
                v = in[(((size_t)(b * CIN + ci0 + c) * DD_ + id) * HH_ + ih) * WW_ + iw];
            s_in[i] = v;
        }
        // weights: s_w[(c*27+k)*32+co] = wgt[(co*CIN + ci0+c)*27 + k]
        for (int i = tid; i < CC * 27 * 32; i += 256) {
            int co = i & 31;
            int ck = i >> 5;
            int c  = ck / 27;
            int k  = ck % 27;
            s_w[i] = wgt[((size_t)co * CIN + ci0 + c) * 27 + k];
        }
        __syncthreads();

        #pragma unroll 1
        for (int c = 0; c < CC; ++c) {
            #pragma unroll
            for (int kd = 0; kd < 3; ++kd)
            #pragma unroll
            for (int kh = 0; kh < 3; ++kh) {
                // 6-wide input windows for both (d,h) positions, broadcast-packed
                uint64_t bcast[2][6];
                #pragma unroll
                for (int i = 0; i < 2; ++i) {
                    const int dhi = dh2 * 2 + i;
                    const int dl = dhi >> 2, hl = dhi & 3;
                    const float* base =
                        &s_in[c * SIN_C + (dl + kd) * SIN_H + (hl + kh) * SW_ROW + wb];
                    float4 a  = *reinterpret_cast<const float4*>(base);
                    float2 bq = *reinterpret_cast<const float2*>(base + 4);
                    PACK2(bcast[i][0], a.x,  a.x);
                    PACK2(bcast[i][1], a.y,  a.y);
                    PACK2(bcast[i][2], a.z,  a.z);
                    PACK2(bcast[i][3], a.w,  a.w);
                    PACK2(bcast[i][4], bq.x, bq.x);
                    PACK2(bcast[i][5], bq.y, bq.y);
                }
                #pragma unroll
                for (int kw = 0; kw < 3; ++kw) {
                    const int k = (kd * 3 + kh) * 3 + kw;
                    #pragma unroll
                    for (int op = 0; op < 4; ++op) {
                        uint64_t wp = *reinterpret_cast<const uint64_t*>(
                            &s_w[(c * 27 + k) * 32 + cob + 2 * op]);
                        #pragma unroll
                        for (int i = 0; i < 2; ++i)
                            #pragma unroll
                            for (int j = 0; j < 4; ++j)
                                FFMA2(acc2[i][op][j], bcast[i][kw + j], wp);
                    }
                }
            }
        }
        __syncthreads();
    }

    // epilogue: BN + ReLU, float4 stores per output channel
    #pragma unroll
    for (int op = 0; op < 4; ++op) {
        const int co0 = cob + 2 * op;
        const float inv0 = gamma[co0] * rsqrtf(var[co0] + 1e-5f);
        const float sh0  = beta[co0] - mean[co0] * inv0;
        const float inv1 = gamma[co0+1] * rsqrtf(var[co0+1] + 1e-5f);
        const float sh1  = beta[co0+1] - mean[co0+1] * inv1;
        #pragma unroll
        for (int i = 0; i < 2; ++i) {
            const int dhi = dh2 * 2 + i;
            const int dl = dhi >> 2, hl = dhi & 3;
            float lo[4], hi[4];
            #pragma unroll
            for (int j = 0; j < 4; ++j) UNPACK2(lo[j], hi[j], acc2[i][op][j]);
            float4 v0, v1;
            v0.x = fmaxf(lo[0]*inv0+sh0, 0.f); v0.y = fmaxf(lo[1]*inv0+sh0, 0.f);
            v0.z = fmaxf(lo[2]*inv0+sh0, 0.f); v0.w = fmaxf(lo[3]*inv0+sh0, 0.f);
            v1.x = fmaxf(hi[0]*inv1+sh1, 0.f); v1.y = fmaxf(hi[1]*inv1+sh1, 0.f);
            v1.z = fmaxf(hi[2]*inv1+sh1, 0.f); v1.w = fmaxf(hi[3]*inv1+sh1, 0.f);
            size_t o0 = (((size_t)(b * CO + co0)   * DD_ + d0 + dl) * HH_ + h0 + hl) * WW_ + w0 + wb;
            size_t o1 = (((size_t)(b * CO + co0+1) * DD_ + d0 + dl) * HH_ + h0 + hl) * WW_ + w0 + wb;
            *reinterpret_cast<float4*>(out + o0) = v0;
            *reinterpret_cast<float4*>(out + o1) = v1;
        }
    }
}

// ---------------------------------------------------------------------------

extern "C" void kernel_launch(void* const* d_in, const int* in_sizes, int n_in,
                              void* d_out, int out_size)
{
    const float* lg = (const float*)d_in[0];
    const float* rg = (const float*)d_in[1];
    const float* lc = (const float*)d_in[2];
    const float* rc = (const float*)d_in[3];
    const float* w1 = (const float*)d_in[4];
    const float* g1 = (const float*)d_in[5];
    const float* b1 = (const float*)d_in[6];
    const float* m1 = (const float*)d_in[7];
    const float* v1 = (const float*)d_in[8];
    const float* w2 = (const float*)d_in[9];
    const float* g2 = (const float*)d_in[10];
    const float* b2 = (const float*)d_in[11];
    const float* m2 = (const float*)d_in[12];
    const float* v2 = (const float*)d_in[13];
    float* out = (float*)d_out;

    float* vol = nullptr;
    float* x1  = nullptr;
    cudaGetSymbolAddress((void**)&vol, g_vol);
    cudaGetSymbolAddress((void**)&x1,  g_x1);

    // 1) cost volume (split by chunk for occupancy)
    dim3 gv(BB * HH_, 11);
    build_volume_kernel<<<gv, 256>>>(lg, rg, lc, rc);

    // 2) conv1 + BN + ReLU  (64 -> 32)
    dim3 grid(4, 16, BB * 12);
    conv3d_bn_relu<CIN1><<<grid, 256>>>(vol, w1, g1, b1, m1, v1, x1);

    // 3) conv2 + BN + ReLU  (32 -> 32)
    conv3d_bn_relu<CO><<<grid, 256>>>(x1, w2, g2, b2, m2, v2, out);
}